// round 13
// baseline (speedup 1.0000x reference)
#include <cuda_runtime.h>
#include <cuda_bf16.h>
#include <cuda_fp16.h>
#include <cstdint>

#define H 1024
#define W 1024
#define HID 256
#define C 3

typedef unsigned long long u64t;

// ---------------------------------------------------------------------------
// global scratch
// ---------------------------------------------------------------------------
__device__ __align__(16) __half g_fxh[H * HID];
__device__ __align__(16) __half g_fyh[W * HID];
// qw1 as fp16, SW128-swizzled K-major tiles. chunk c (k0=64c): 32KB at c*32768
__device__ __align__(16) unsigned char g_qpack[4 * 32768];
// partial GEMV sums: [half][c][j][i]  (2 x 3M floats = 25MB)
#define PQ (3 * 1024 * 1024)
__device__ __align__(16) float g_part[2 * PQ];

// ---------------- fast sine (scalar, branch kernel) ------------------------
__device__ __forceinline__ float fast_sin(float x) {
    const float INV_PI = 0.318309886183790671f;
    float k = rintf(x * INV_PI);
    float r = fmaf(-k, 3.14159274101257324f, x);
    r = fmaf(k, 8.74227765734758577e-8f, r);
    float s = r * r;
    float p = fmaf(s, 2.75573192e-6f, -1.98412698e-4f);
    p = fmaf(s, p, 8.33333333e-3f);
    p = fmaf(s, p, -1.66666667e-1f);
    float res = fmaf(s * r, p, r);
    int ki = (int)k;
    return (ki & 1) ? -res : res;
}

// ---------------- f32x2 packed helpers -------------------------------------
__device__ __forceinline__ u64t pk2(float lo, float hi) {
    u64t r;
    asm("mov.b64 %0, {%1, %2};" : "=l"(r)
        : "r"(__float_as_uint(lo)), "r"(__float_as_uint(hi)));
    return r;
}
__device__ __forceinline__ void upk2(u64t v, float& lo, float& hi) {
    uint32_t a, b;
    asm("mov.b64 {%0, %1}, %2;" : "=r"(a), "=r"(b) : "l"(v));
    lo = __uint_as_float(a);
    hi = __uint_as_float(b);
}
__device__ __forceinline__ u64t f2fma(u64t a, u64t b, u64t c) {
    u64t r;
    asm("fma.rn.f32x2 %0, %1, %2, %3;" : "=l"(r) : "l"(a), "l"(b), "l"(c));
    return r;
}

// ---------------- misc PTX helpers -----------------------------------------
__device__ __forceinline__ uint32_t smem_u32(const void* p) {
    uint32_t a;
    asm("{ .reg .u64 t; cvta.to.shared.u64 t, %1; cvt.u32.u64 %0, t; }"
        : "=r"(a) : "l"(p));
    return a;
}
__device__ __forceinline__ void ldsm_x4(uint32_t* r, uint32_t addr) {
    asm volatile("ldmatrix.sync.aligned.m8n8.x4.shared.b16 {%0,%1,%2,%3}, [%4];"
                 : "=r"(r[0]), "=r"(r[1]), "=r"(r[2]), "=r"(r[3]) : "r"(addr));
}
__device__ __forceinline__ void mma_f16(float* c, const uint32_t* a,
                                        const uint32_t* b) {
    asm volatile(
        "mma.sync.aligned.m16n8k16.row.col.f32.f16.f16.f32 "
        "{%0,%1,%2,%3}, {%4,%5,%6,%7}, {%8,%9}, {%0,%1,%2,%3};"
        : "+f"(c[0]), "+f"(c[1]), "+f"(c[2]), "+f"(c[3])
        : "r"(a[0]), "r"(a[1]), "r"(a[2]), "r"(a[3]), "r"(b[0]), "r"(b[1]));
}
#define CP_ASYNC16(dst, src) \
    asm volatile("cp.async.cg.shared.global [%0], [%1], 16;" \
                 :: "r"(dst), "l"(src))
#define CP_COMMIT()  asm volatile("cp.async.commit_group;")
#define CP_WAIT0()   asm volatile("cp.async.wait_group 0;" ::: "memory")

__device__ __forceinline__ uint32_t packh2(float hi, float lo) {
    uint32_t r;
    asm("cvt.rn.f16x2.f32 %0, %1, %2;" : "=r"(r) : "f"(hi), "f"(lo));
    return r;
}
__device__ __forceinline__ uint32_t hmul2(uint32_t a, uint32_t b) {
    uint32_t r;
    asm("mul.rn.f16x2 %0, %1, %2;" : "=r"(r) : "r"(a), "r"(b));
    return r;
}

// ---------------- kernel 0: pack+swizzle qw1 to fp16 -----------------------
__global__ void pack_qw1_kernel(const float* __restrict__ qw1) {
    int idx = blockIdx.x * 256 + threadIdx.x;
    int n = idx >> 7;
    int kw = idx & 127;
    int k = kw * 2;
    int cch = k >> 6;
    int kk = k & 63;
    float w0 = qw1[n * HID + k];
    float w1 = qw1[n * HID + k + 1];
    uint32_t hw = packh2(w1, w0);
    uint32_t off = ((n >> 3) << 10) + ((n & 7) << 7) + kk * 2;
    uint32_t sw = off ^ ((off >> 3) & 0x70);
    *(uint32_t*)(g_qpack + cch * 32768 + sw) = hw;
}

// ---------------- kernel 1: branch + premerge (fp16 outputs) ---------------
__device__ __forceinline__ void dense_layer(
    const float (*hin)[HID], float (*hout)[HID],
    const float* __restrict__ pw, const float* __restrict__ pb, int t)
{
    float acc[16];
    float bias = pb[t];
#pragma unroll
    for (int r = 0; r < 16; r++) acc[r] = bias;
    const float4* pw4 = (const float4*)pw;
#pragma unroll 4
    for (int k4 = 0; k4 < HID / 4; k4++) {
        float4 w4 = pw4[t * (HID / 4) + k4];
#pragma unroll
        for (int r = 0; r < 16; r++) {
            float4 hv = *(const float4*)&hin[r][k4 * 4];
            acc[r] = fmaf(hv.x, w4.x, acc[r]);
            acc[r] = fmaf(hv.y, w4.y, acc[r]);
            acc[r] = fmaf(hv.z, w4.z, acc[r]);
            acc[r] = fmaf(hv.w, w4.w, acc[r]);
        }
    }
#pragma unroll
    for (int r = 0; r < 16; r++) hout[r][t] = fast_sin(acc[r]);
}

__global__ void branch_kernel(
    const float* __restrict__ x, const float* __restrict__ y,
    const float* __restrict__ bw0, const float* __restrict__ bb0,
    const float* __restrict__ bw1, const float* __restrict__ bb1,
    const float* __restrict__ pw1, const float* __restrict__ pb1,
    const float* __restrict__ pw2, const float* __restrict__ pb2)
{
    int axis = blockIdx.y;
    const float* coord = axis ? y : x;
    const float* bw = axis ? bw1 : bw0;
    const float* bb = axis ? bb1 : bb0;
    __half* outf = axis ? g_fyh : g_fxh;
    int r0 = blockIdx.x * 16;
    int t = threadIdx.x;

    __shared__ __align__(16) float hA[16][HID];
    __shared__ __align__(16) float hB[16][HID];

    float w = bw[t], b = bb[t];
#pragma unroll
    for (int r = 0; r < 16; r++)
        hA[r][t] = fast_sin(fmaf(coord[r0 + r], w, b));
    __syncthreads();
    dense_layer(hA, hB, pw1, pb1, t);
    __syncthreads();
    dense_layer(hB, hA, pw2, pb2, t);
    __syncthreads();
#pragma unroll
    for (int r = 0; r < 16; r++)
        outf[(r0 + r) * HID + t] = __float2half_rn(hA[r][t]);
}

// ---------------- kernel 2: N-split, 2 CTAs/SM -----------------------------
// grid (8, 2, 128): i0 = bx*128, n-half = by (n 128), j in [bz*8, bz*8+8).
// 256 threads = 8 warps (4M x 2N), warp tile 32m x 64n (same as before).
// B half (64KB) resident; A double-buffered; barrier every step; serial
// epilogue bubbles hidden by the co-resident CTA on the same SM.
// GEMV is partial (n-half); raw partials to g_part; reduce kernel finishes.
// SMEM map (102KB):
//   0     qb1s 512B | 512 qw2s 1536B | 2048 fyh 2x512B | 3072 part 3KB
//   6144  B 64KB (4 x 16KB) | 71680 A 2 x 16KB
#define SM_QB1  0
#define SM_QW2  512
#define SM_FYH  2048
#define SM_PART 3072
#define SM_B    6144
#define SM_A    71680
#define SMEM_TOTAL 104448

__global__ __launch_bounds__(256, 2)
void fused_mma_kernel(const float* __restrict__ qb1,
                      const float* __restrict__ qw2)
{
    extern __shared__ __align__(1024) char smem[];
    const uint32_t sb = smem_u32(smem);
    const int tid = threadIdx.x;
    const int wid = tid >> 5;
    const int lane = tid & 31;
    const int wm = wid & 3;              // 4 m-warps
    const int wn = wid >> 2;             // 2 n-warps
    const int m0w = wm * 32;
    const int n0w = wn * 64;             // local n base (0 or 64)
    const int i0 = blockIdx.x * 128;
    const int half = blockIdx.y;
    const int j0 = blockIdx.z * 8;

    float* qb1s = (float*)(smem + SM_QB1);       // 128 (this half)
    float* qw2s = (float*)(smem + SM_QW2);       // 3 x 128 (this half)
    uint32_t* fyhs = (uint32_t*)(smem + SM_FYH); // 2 bufs x 128 h2 words
    float* part = (float*)(smem + SM_PART);      // [128][2][3]

    // ---- one-time staging: B half via cp.async, smalls, fyh(j0) ----
    {
        const char* src = (const char*)g_qpack + half * 16384;
#pragma unroll
        for (int c = 0; c < 4; c++) {
            uint32_t dst = sb + SM_B + c * 16384;
            const char* s = src + c * 32768;
#pragma unroll
            for (int e = 0; e < 4; e++) {
                uint32_t off = (uint32_t)(e * 256 + tid) * 16;
                CP_ASYNC16(dst + off, s + off);
            }
        }
        CP_COMMIT();
    }
    if (tid < 128) qb1s[tid] = qb1[half * 128 + tid];
    else fyhs[tid - 128] = ((const uint32_t*)(g_fyh + (size_t)j0 * HID))[tid - 128];
    for (int e = tid; e < 3 * 128; e += 256)
        qw2s[e] = qw2[(e >> 7) * HID + half * 128 + (e & 127)];
    __syncthreads();         // smalls/fyh visible before builds

    // ---- A build: thread -> row rA = tid/2, 64B segment (tid&1) ----
    const int rA = tid >> 1;
    const int sgE = (tid & 1) * 32;              // element offset in chunk row
    const uint32_t segB = (uint32_t)((tid & 1) * 64);
    const uint32_t rowoff = ((rA >> 3) << 10) + ((rA & 7) << 7);
    const uint32_t rxor = (rA & 7) << 4;

    uint4 pf0, pf1, pf2, pf3;                    // 32 fx halves prefetched
    auto load_pf = [&](int c) {
        const uint4* p = (const uint4*)(g_fxh + (size_t)(i0 + rA) * HID + c * 64 + sgE);
        pf0 = p[0]; pf1 = p[1]; pf2 = p[2]; pf3 = p[3];
    };
    auto build_A = [&](int abuf, int fyb, int c) {
        const uint4* fyp = (const uint4*)((char*)fyhs + fyb * 512 + (c * 64 + sgE) * 2);
        uint4 g0 = fyp[0], g1 = fyp[1], g2 = fyp[2], g3 = fyp[3];
        uint4 o0, o1, o2, o3;
        o0.x = hmul2(pf0.x, g0.x); o0.y = hmul2(pf0.y, g0.y);
        o0.z = hmul2(pf0.z, g0.z); o0.w = hmul2(pf0.w, g0.w);
        o1.x = hmul2(pf1.x, g1.x); o1.y = hmul2(pf1.y, g1.y);
        o1.z = hmul2(pf1.z, g1.z); o1.w = hmul2(pf1.w, g1.w);
        o2.x = hmul2(pf2.x, g2.x); o2.y = hmul2(pf2.y, g2.y);
        o2.z = hmul2(pf2.z, g2.z); o2.w = hmul2(pf2.w, g2.w);
        o3.x = hmul2(pf3.x, g3.x); o3.y = hmul2(pf3.y, g3.y);
        o3.z = hmul2(pf3.z, g3.z); o3.w = hmul2(pf3.w, g3.w);
        char* base = smem + SM_A + abuf * 16384;
        *(uint4*)(base + rowoff + ((segB + 0) ^ rxor)) = o0;
        *(uint4*)(base + rowoff + ((segB + 16) ^ rxor)) = o1;
        *(uint4*)(base + rowoff + ((segB + 32) ^ rxor)) = o2;
        *(uint4*)(base + rowoff + ((segB + 48) ^ rxor)) = o3;
    };

    // ---- LDSM per-thread row/col components ----
    uint32_t rowA[2], xorA[2], colA;
    uint32_t rowB[4], xorB[4], colB;
    colA = (uint32_t)((lane >> 4) << 4);
#pragma unroll
    for (int mb = 0; mb < 2; mb++) {
        int r = m0w + mb * 16 + (lane & 15);
        rowA[mb] = ((r >> 3) << 10) + ((r & 7) << 7);
        xorA[mb] = (uint32_t)((r & 7) << 4);
    }
    colB = (uint32_t)(((lane >> 3) & 1) << 4);
#pragma unroll
    for (int nb = 0; nb < 4; nb++) {
        int r = n0w + nb * 16 + (lane & 7) + ((lane >> 4) << 3);
        rowB[nb] = ((r >> 3) << 10) + ((r & 7) << 7);
        xorB[nb] = (uint32_t)((r & 7) << 4);
    }

    float acc[2][8][4];
#pragma unroll
    for (int mb = 0; mb < 2; mb++)
#pragma unroll
        for (int nx = 0; nx < 8; nx++)
#pragma unroll
            for (int e = 0; e < 4; e++) acc[mb][nx][e] = 0.f;

    // prologue: build A(t=0); prefetch for t=1; wait B.
    load_pf(0);
    build_A(0, 0, 0);
    load_pf(1);
    CP_WAIT0();

    // ---- flat pipeline: t = j*4 + c ; barrier every step ----
    for (int t = 0; t < 32; t++) {
        const int jj = t >> 2;
        const int c = t & 3;
        __syncthreads();

        if (c == 0) {
            if (jj >= 1) {
                // write raw partials of j-1 to global
                for (int e = tid; e < 384; e += 256) {
                    int m = e & 127;
                    int cc = e >> 7;
                    float s = part[(m * 2 + 0) * 3 + cc] +
                              part[(m * 2 + 1) * 3 + cc];
                    g_part[half * PQ + (cc << 20) + ((j0 + jj - 1) << 10) + i0 + m] = s;
                }
            }
            if (jj < 7 && tid < 128)
                fyhs[((jj + 1) & 1) * 128 + tid] =
                    ((const uint32_t*)(g_fyh + (size_t)(j0 + jj + 1) * HID))[tid];
        }

        // MMA chunk c: A from buf t&1, B chunk at SM_B + c*16KB
        {
            const uint32_t astg = sb + SM_A + (uint32_t)(t & 1) * 16384;
            const uint32_t bstg = sb + SM_B + (uint32_t)c * 16384;
#pragma unroll
            for (int s = 0; s < 4; s++) {
                const uint32_t ks = (uint32_t)(s * 32);
                uint32_t ah[2][4];
#pragma unroll
                for (int mb = 0; mb < 2; mb++)
                    ldsm_x4(ah[mb], astg + rowA[mb] + ((colA + ks) ^ xorA[mb]));
#pragma unroll
                for (int nb = 0; nb < 4; nb++) {
                    uint32_t bh[4];
                    ldsm_x4(bh, bstg + rowB[nb] + ((colB + ks) ^ xorB[nb]));
#pragma unroll
                    for (int mb = 0; mb < 2; mb++) {
                        mma_f16(acc[mb][nb * 2 + 0], ah[mb], bh + 0);
                        mma_f16(acc[mb][nb * 2 + 1], ah[mb], bh + 2);
                    }
                }
            }
        }

        // build A for t+1; prefetch fx for t+2
        if (t < 31)
            build_A((t + 1) & 1, ((t + 1) >> 2) & 1, (t + 1) & 3);
        if (t < 30)
            load_pf((t + 2) & 3);

        // ---- epilogue at end of each j: bias + MUFU sin + partial GEMV ----
        if (c == 3) {
#pragma unroll
            for (int mb = 0; mb < 2; mb++) {
                u64t pr[6];
#pragma unroll
                for (int e = 0; e < 6; e++) pr[e] = pk2(0.f, 0.f);
#pragma unroll
                for (int nx = 0; nx < 8; nx++) {
                    int n = n0w + nx * 8 + (lane & 3) * 2;
                    float b0 = qb1s[n], b1 = qb1s[n + 1];
                    u64t w0 = *(const u64t*)(qw2s + n);
                    u64t w1 = *(const u64t*)(qw2s + 128 + n);
                    u64t w2 = *(const u64t*)(qw2s + 256 + n);
#pragma unroll
                    for (int rh = 0; rh < 2; rh++) {
                        float s0 = acc[mb][nx][rh * 2] + b0;
                        float s1 = acc[mb][nx][rh * 2 + 1] + b1;
                        acc[mb][nx][rh * 2] = 0.f;
                        acc[mb][nx][rh * 2 + 1] = 0.f;
                        u64t h2 = pk2(__sinf(s0), __sinf(s1));
                        pr[rh * 3 + 0] = f2fma(h2, w0, pr[rh * 3 + 0]);
                        pr[rh * 3 + 1] = f2fma(h2, w1, pr[rh * 3 + 1]);
                        pr[rh * 3 + 2] = f2fma(h2, w2, pr[rh * 3 + 2]);
                    }
                }
                float ps[6];
#pragma unroll
                for (int e = 0; e < 6; e++) {
                    float lo, hi;
                    upk2(pr[e], lo, hi);
                    ps[e] = lo + hi;
                }
#pragma unroll
                for (int d = 1; d <= 2; d <<= 1)
#pragma unroll
                    for (int e = 0; e < 6; e++)
                        ps[e] += __shfl_xor_sync(0xffffffffu, ps[e], d);
                if ((lane & 3) == 0) {
#pragma unroll
                    for (int rh = 0; rh < 2; rh++) {
                        int m = m0w + mb * 16 + (lane >> 2) + rh * 8;
#pragma unroll
                        for (int cc = 0; cc < 3; cc++)
                            part[(m * 2 + wn) * 3 + cc] = ps[rh * 3 + cc];
                    }
                }
            }
        }
    }

    // ---- tail: partials for j7 ----
    __syncthreads();
    for (int e = tid; e < 384; e += 256) {
        int m = e & 127;
        int cc = e >> 7;
        float s = part[(m * 2 + 0) * 3 + cc] + part[(m * 2 + 1) * 3 + cc];
        g_part[half * PQ + (cc << 20) + ((j0 + 7) << 10) + i0 + m] = s;
    }
}

// ---------------- kernel 3: reduce halves + sigmoid ------------------------
__global__ void reduce_kernel(const float* __restrict__ qb2,
                              float* __restrict__ out)
{
    int e4 = (blockIdx.x * 256 + threadIdx.x) * 4;   // element base
    int cc = e4 >> 20;
    float b = __ldg(&qb2[cc]);
    float4 a = *(const float4*)(g_part + e4);
    float4 d = *(const float4*)(g_part + PQ + e4);
    float4 o;
    o.x = 1.f / (1.f + __expf(-(b + a.x + d.x)));
    o.y = 1.f / (1.f + __expf(-(b + a.y + d.y)));
    o.z = 1.f / (1.f + __expf(-(b + a.z + d.z)));
    o.w = 1.f / (1.f + __expf(-(b + a.w + d.w)));
    *(float4*)(out + e4) = o;
}

// ---------------------------------------------------------------------------
extern "C" void kernel_launch(void* const* d_in, const int* in_sizes, int n_in,
                              void* d_out, int out_size)
{
    const float* x   = (const float*)d_in[0];
    const float* y   = (const float*)d_in[1];
    const float* bw0 = (const float*)d_in[2];
    const float* bb0 = (const float*)d_in[3];
    const float* bw1 = (const float*)d_in[4];
    const float* bb1 = (const float*)d_in[5];
    const float* pw1 = (const float*)d_in[6];
    const float* pb1 = (const float*)d_in[7];
    const float* pw2 = (const float*)d_in[8];
    const float* pb2 = (const float*)d_in[9];
    const float* qw1 = (const float*)d_in[10];
    const float* qb1 = (const float*)d_in[11];
    const float* qw2 = (const float*)d_in[12];
    const float* qb2 = (const float*)d_in[13];
    float* out = (float*)d_out;

    cudaFuncSetAttribute(fused_mma_kernel,
                         cudaFuncAttributeMaxDynamicSharedMemorySize, SMEM_TOTAL);

    pack_qw1_kernel<<<128, 256>>>(qw1);
    branch_kernel<<<dim3(H / 16, 2), 256>>>(x, y, bw0, bb0, bw1, bb1,
                                            pw1, pb1, pw2, pb2);
    fused_mma_kernel<<<dim3(8, 2, 128), 256, SMEM_TOTAL>>>(qb1, qw2);
    reduce_kernel<<<C * H * W / 1024, 256>>>(qb2, out);
}

// round 14
// speedup vs baseline: 1.1747x; 1.1747x over previous
#include <cuda_runtime.h>
#include <cuda_bf16.h>
#include <cuda_fp16.h>
#include <cstdint>

#define H 1024
#define W 1024
#define HID 256
#define C 3

typedef unsigned long long u64t;

// ---------------------------------------------------------------------------
// global scratch
// ---------------------------------------------------------------------------
__device__ __align__(16) __half g_fxh[H * HID];
__device__ __align__(16) __half g_fyh[W * HID];
// qw1 as fp16, SW128-swizzled K-major tiles. chunk c (k0=64c): 32KB at c*32768
__device__ __align__(16) unsigned char g_qpack[4 * 32768];

// ---------------- fast sine (scalar, branch kernel) ------------------------
__device__ __forceinline__ float fast_sin(float x) {
    const float INV_PI = 0.318309886183790671f;
    float k = rintf(x * INV_PI);
    float r = fmaf(-k, 3.14159274101257324f, x);
    r = fmaf(k, 8.74227765734758577e-8f, r);
    float s = r * r;
    float p = fmaf(s, 2.75573192e-6f, -1.98412698e-4f);
    p = fmaf(s, p, 8.33333333e-3f);
    p = fmaf(s, p, -1.66666667e-1f);
    float res = fmaf(s * r, p, r);
    int ki = (int)k;
    return (ki & 1) ? -res : res;
}

// ---------------- f32x2 packed helpers -------------------------------------
__device__ __forceinline__ u64t pk2(float lo, float hi) {
    u64t r;
    asm("mov.b64 %0, {%1, %2};" : "=l"(r)
        : "r"(__float_as_uint(lo)), "r"(__float_as_uint(hi)));
    return r;
}
__device__ __forceinline__ void upk2(u64t v, float& lo, float& hi) {
    uint32_t a, b;
    asm("mov.b64 {%0, %1}, %2;" : "=r"(a), "=r"(b) : "l"(v));
    lo = __uint_as_float(a);
    hi = __uint_as_float(b);
}
__device__ __forceinline__ u64t f2fma(u64t a, u64t b, u64t c) {
    u64t r;
    asm("fma.rn.f32x2 %0, %1, %2, %3;" : "=l"(r) : "l"(a), "l"(b), "l"(c));
    return r;
}

// ---------------- misc PTX helpers -----------------------------------------
__device__ __forceinline__ uint32_t smem_u32(const void* p) {
    uint32_t a;
    asm("{ .reg .u64 t; cvta.to.shared.u64 t, %1; cvt.u32.u64 %0, t; }"
        : "=r"(a) : "l"(p));
    return a;
}
__device__ __forceinline__ void ldsm_x4(uint32_t* r, uint32_t addr) {
    asm volatile("ldmatrix.sync.aligned.m8n8.x4.shared.b16 {%0,%1,%2,%3}, [%4];"
                 : "=r"(r[0]), "=r"(r[1]), "=r"(r[2]), "=r"(r[3]) : "r"(addr));
}
__device__ __forceinline__ void mma_f16(float* c, const uint32_t* a,
                                        const uint32_t* b) {
    asm volatile(
        "mma.sync.aligned.m16n8k16.row.col.f32.f16.f16.f32 "
        "{%0,%1,%2,%3}, {%4,%5,%6,%7}, {%8,%9}, {%0,%1,%2,%3};"
        : "+f"(c[0]), "+f"(c[1]), "+f"(c[2]), "+f"(c[3])
        : "r"(a[0]), "r"(a[1]), "r"(a[2]), "r"(a[3]), "r"(b[0]), "r"(b[1]));
}
#define CP_ASYNC16(dst, src) \
    asm volatile("cp.async.cg.shared.global [%0], [%1], 16;" \
                 :: "r"(dst), "l"(src))
#define CP_COMMIT()  asm volatile("cp.async.commit_group;")
#define CP_WAIT0()   asm volatile("cp.async.wait_group 0;" ::: "memory")

__device__ __forceinline__ uint32_t packh2(float hi, float lo) {
    uint32_t r;
    asm("cvt.rn.f16x2.f32 %0, %1, %2;" : "=r"(r) : "f"(hi), "f"(lo));
    return r;
}
__device__ __forceinline__ uint32_t hmul2(uint32_t a, uint32_t b) {
    uint32_t r;
    asm("mul.rn.f16x2 %0, %1, %2;" : "=r"(r) : "r"(a), "r"(b));
    return r;
}

// ---------------- kernel 0: pack+swizzle qw1 to fp16 -----------------------
__global__ void pack_qw1_kernel(const float* __restrict__ qw1) {
    int idx = blockIdx.x * 256 + threadIdx.x;
    int n = idx >> 7;
    int kw = idx & 127;
    int k = kw * 2;
    int cch = k >> 6;
    int kk = k & 63;
    float w0 = qw1[n * HID + k];
    float w1 = qw1[n * HID + k + 1];
    uint32_t hw = packh2(w1, w0);
    uint32_t off = ((n >> 3) << 10) + ((n & 7) << 7) + kk * 2;
    uint32_t sw = off ^ ((off >> 3) & 0x70);
    *(uint32_t*)(g_qpack + cch * 32768 + sw) = hw;
}

// ---------------- kernel 1: branch + premerge (fp16 outputs) ---------------
__device__ __forceinline__ void dense_layer(
    const float (*hin)[HID], float (*hout)[HID],
    const float* __restrict__ pw, const float* __restrict__ pb, int t)
{
    float acc[16];
    float bias = pb[t];
#pragma unroll
    for (int r = 0; r < 16; r++) acc[r] = bias;
    const float4* pw4 = (const float4*)pw;
#pragma unroll 4
    for (int k4 = 0; k4 < HID / 4; k4++) {
        float4 w4 = pw4[t * (HID / 4) + k4];
#pragma unroll
        for (int r = 0; r < 16; r++) {
            float4 hv = *(const float4*)&hin[r][k4 * 4];
            acc[r] = fmaf(hv.x, w4.x, acc[r]);
            acc[r] = fmaf(hv.y, w4.y, acc[r]);
            acc[r] = fmaf(hv.z, w4.z, acc[r]);
            acc[r] = fmaf(hv.w, w4.w, acc[r]);
        }
    }
#pragma unroll
    for (int r = 0; r < 16; r++) hout[r][t] = fast_sin(acc[r]);
}

__global__ void branch_kernel(
    const float* __restrict__ x, const float* __restrict__ y,
    const float* __restrict__ bw0, const float* __restrict__ bb0,
    const float* __restrict__ bw1, const float* __restrict__ bb1,
    const float* __restrict__ pw1, const float* __restrict__ pb1,
    const float* __restrict__ pw2, const float* __restrict__ pb2)
{
    int axis = blockIdx.y;
    const float* coord = axis ? y : x;
    const float* bw = axis ? bw1 : bw0;
    const float* bb = axis ? bb1 : bb0;
    __half* outf = axis ? g_fyh : g_fxh;
    int r0 = blockIdx.x * 16;
    int t = threadIdx.x;

    __shared__ __align__(16) float hA[16][HID];
    __shared__ __align__(16) float hB[16][HID];

    float w = bw[t], b = bb[t];
#pragma unroll
    for (int r = 0; r < 16; r++)
        hA[r][t] = fast_sin(fmaf(coord[r0 + r], w, b));
    __syncthreads();
    dense_layer(hA, hB, pw1, pb1, t);
    __syncthreads();
    dense_layer(hB, hA, pw2, pb2, t);
    __syncthreads();
#pragma unroll
    for (int r = 0; r < 16; r++)
        outf[(r0 + r) * HID + t] = __float2half_rn(hA[r][t]);
}

// ---------------- kernel 2: M=128, B-resident, MUFU epilogue ---------------
// grid (8, 128): i0 = bx*128, j in [by*8, by*8+8). 512 threads = 16 warps
// (4M x 4N), warp tile 32x64. A quad-buffered, __syncthreads every 2 steps.
// jj outer loop, c inner unrolled -> all buffer indices compile-time.
// SMEM map:
//   0      qb1s 1K | 1024 qw2s 3K | 4096 qb2s | 4608 fyh 2x512B
//   5632   part[128][4][3] f32 (6KB)
//   13312  B 128KB (4 x 32KB)
//   144384 A 4 x 16KB
#define SM_QB1  0
#define SM_QW2  1024
#define SM_QB2  4096
#define SM_FYH  4608
#define SM_PART 5632
#define SM_B    13312
#define SM_A    144384
#define SMEM_TOTAL 209920

__global__ __launch_bounds__(512, 1)
void fused_mma_kernel(
    const float* __restrict__ qb1, const float* __restrict__ qw2,
    const float* __restrict__ qb2, float* __restrict__ out)
{
    extern __shared__ __align__(1024) char smem[];
    const uint32_t sb = smem_u32(smem);
    const int tid = threadIdx.x;
    const int wid = tid >> 5;
    const int lane = tid & 31;
    const int wm = wid & 3;
    const int wn = wid >> 2;
    const int m0w = wm * 32;
    const int n0w = wn * 64;
    const int i0 = blockIdx.x * 128;
    const int j0 = blockIdx.y * 8;

    float* qb1s = (float*)(smem + SM_QB1);
    float* qw2s = (float*)(smem + SM_QW2);
    float* qb2s = (float*)(smem + SM_QB2);
    uint32_t* fyhs = (uint32_t*)(smem + SM_FYH);   // 2 buffers x 128 h2 words
    float* part = (float*)(smem + SM_PART);

    // ---- one-time staging: B via cp.async, smalls, fyh(j0) ----
    {
        const char* src = (const char*)g_qpack;
        uint32_t dst = sb + SM_B;
#pragma unroll
        for (int e = 0; e < 16; e++) {
            uint32_t off = (uint32_t)(e * 512 + tid) * 16;
            CP_ASYNC16(dst + off, src + off);
        }
        CP_COMMIT();
    }
    if (tid < 256) qb1s[tid] = qb1[tid];
    if (tid >= 256 && tid < 384)
        fyhs[tid - 256] = ((const uint32_t*)(g_fyh + (size_t)j0 * HID))[tid - 256];
    for (int e = tid; e < 3 * HID; e += 512) qw2s[e] = qw2[e];
    if (tid < 3) qb2s[tid] = qb2[tid];
    __syncthreads();          // fyhs/qb1s/qw2s visible before any A-build

    // ---- A build config: row rA = tid/4, k-quarter kq ----
    const int rA = tid >> 2;
    const int kq = (tid & 3) << 4;             // k offset within 64-chunk
    const uint32_t rowoff = ((rA >> 3) << 10) + ((rA & 7) << 7);
    const uint32_t rxor = (rA & 7) << 4;

    uint4 pf0, pf1;                            // prefetched fx fp16 (16 halves)
    auto load_pf = [&](int c) {
        const uint4* p = (const uint4*)(g_fxh + (size_t)(i0 + rA) * HID + c * 64 + kq);
        pf0 = p[0];
        pf1 = p[1];
    };
    auto build_A_pf = [&](int abuf, int fyb, int c) {
        const uint4* fyp = (const uint4*)((char*)fyhs + fyb * 512 + (c * 64 + kq) * 2);
        uint4 g0 = fyp[0], g1 = fyp[1];
        uint32_t hw[8];
        hw[0] = hmul2(pf0.x, g0.x); hw[1] = hmul2(pf0.y, g0.y);
        hw[2] = hmul2(pf0.z, g0.z); hw[3] = hmul2(pf0.w, g0.w);
        hw[4] = hmul2(pf1.x, g1.x); hw[5] = hmul2(pf1.y, g1.y);
        hw[6] = hmul2(pf1.z, g1.z); hw[7] = hmul2(pf1.w, g1.w);
        char* base = smem + SM_A + abuf * 16384;
        uint32_t c0 = (uint32_t)(kq * 2);
        uint32_t o0 = rowoff + (c0 ^ rxor);
        uint32_t o1 = rowoff + ((c0 + 16) ^ rxor);
        *(uint4*)(base + o0) = make_uint4(hw[0], hw[1], hw[2], hw[3]);
        *(uint4*)(base + o1) = make_uint4(hw[4], hw[5], hw[6], hw[7]);
    };

    // ---- LDSM per-thread row/col components ----
    uint32_t rowA[2], xorA[2], colA;
    uint32_t rowB[4], xorB[4], colB;
    colA = (uint32_t)((lane >> 4) << 4);
#pragma unroll
    for (int mb = 0; mb < 2; mb++) {
        int r = m0w + mb * 16 + (lane & 15);
        rowA[mb] = ((r >> 3) << 10) + ((r & 7) << 7);
        xorA[mb] = (uint32_t)((r & 7) << 4);
    }
    colB = (uint32_t)(((lane >> 3) & 1) << 4);
#pragma unroll
    for (int nb = 0; nb < 4; nb++) {
        int r = n0w + nb * 16 + (lane & 7) + ((lane >> 4) << 3);
        rowB[nb] = ((r >> 3) << 10) + ((r & 7) << 7);
        xorB[nb] = (uint32_t)((r & 7) << 4);
    }

    float acc[2][8][4];
#pragma unroll
    for (int mb = 0; mb < 2; mb++)
#pragma unroll
        for (int nx = 0; nx < 8; nx++)
#pragma unroll
            for (int e = 0; e < 4; e++) acc[mb][nx][e] = 0.f;

    // prologue: build A for t=0 (chunk0) and t=1 (chunk1); prefetch chunk2.
    load_pf(0);
    build_A_pf(0, 0, 0);
    load_pf(1);
    build_A_pf(1, 0, 1);
    load_pf(2);
    CP_WAIT0();                        // all B chunks landed
    __syncthreads();

    // ---- pipeline: jj outer, c inner unrolled (static buffer indices) ----
    for (int jj = 0; jj < 8; jj++) {
#pragma unroll
        for (int c = 0; c < 4; c++) {
            const int t = jj * 4 + c;

            if (c == 0) {
                // final output store for j-1 (part synced at end of t-1)
                if (jj >= 1 && tid < 384) {
                    int m = tid & 127;
                    int cc = tid >> 7;
                    float s = qb2s[cc];
#pragma unroll
                    for (int v = 0; v < 4; v++) s += part[(m * 4 + v) * 3 + cc];
                    out[((unsigned)cc * W + (j0 + jj - 1)) * H + i0 + m] =
                        1.f / (1.f + __expf(-s));
                }
                if (jj < 7 && tid < 128)
                    fyhs[((jj + 1) & 1) * 128 + tid] =
                        ((const uint32_t*)(g_fyh + (size_t)(j0 + jj + 1) * HID))[tid];
            }

            // MMA chunk c: A buf c (static), B chunk c (static)
            {
                const uint32_t astg = sb + SM_A + (uint32_t)(c * 16384);
                const uint32_t bstg = sb + SM_B + (uint32_t)(c * 32768);
#pragma unroll
                for (int s = 0; s < 4; s++) {
                    const uint32_t ks = (uint32_t)(s * 32);
                    uint32_t ah[2][4];
#pragma unroll
                    for (int mb = 0; mb < 2; mb++)
                        ldsm_x4(ah[mb], astg + rowA[mb] + ((colA + ks) ^ xorA[mb]));
#pragma unroll
                    for (int nb = 0; nb < 4; nb++) {
                        uint32_t bh[4];
                        ldsm_x4(bh, bstg + rowB[nb] + ((colB + ks) ^ xorB[nb]));
#pragma unroll
                        for (int mb = 0; mb < 2; mb++) {
                            mma_f16(acc[mb][nb * 2 + 0], ah[mb], bh + 0);
                            mma_f16(acc[mb][nb * 2 + 1], ah[mb], bh + 2);
                        }
                    }
                }
            }

            // build A for t+2 (chunk/buf (c+2)&3, fyb flips at c>=2);
            // prefetch fx for t+3
            if (t < 30)
                build_A_pf((c + 2) & 3, (c < 2) ? (jj & 1) : ((jj + 1) & 1),
                           (c + 2) & 3);
            if (t < 29)
                load_pf((c + 3) & 3);

            // ---- epilogue at end of each j (mb-sequential, pr[6]) ----
            if (c == 3) {
#pragma unroll
                for (int mb = 0; mb < 2; mb++) {
                    u64t pr[6];
#pragma unroll
                    for (int e = 0; e < 6; e++) pr[e] = pk2(0.f, 0.f);
#pragma unroll
                    for (int nx = 0; nx < 8; nx++) {
                        int n = n0w + nx * 8 + (lane & 3) * 2;
                        float b0 = qb1s[n], b1 = qb1s[n + 1];
                        u64t w0 = *(const u64t*)(qw2s + n);
                        u64t w1 = *(const u64t*)(qw2s + 256 + n);
                        u64t w2 = *(const u64t*)(qw2s + 512 + n);
#pragma unroll
                        for (int rh = 0; rh < 2; rh++) {
                            float s0 = acc[mb][nx][rh * 2] + b0;
                            float s1 = acc[mb][nx][rh * 2 + 1] + b1;
                            acc[mb][nx][rh * 2] = 0.f;
                            acc[mb][nx][rh * 2 + 1] = 0.f;
                            u64t h2 = pk2(__sinf(s0), __sinf(s1));
                            pr[rh * 3 + 0] = f2fma(h2, w0, pr[rh * 3 + 0]);
                            pr[rh * 3 + 1] = f2fma(h2, w1, pr[rh * 3 + 1]);
                            pr[rh * 3 + 2] = f2fma(h2, w2, pr[rh * 3 + 2]);
                        }
                    }
                    float ps[6];
#pragma unroll
                    for (int e = 0; e < 6; e++) {
                        float lo, hi;
                        upk2(pr[e], lo, hi);
                        ps[e] = lo + hi;
                    }
#pragma unroll
                    for (int d = 1; d <= 2; d <<= 1)
#pragma unroll
                        for (int e = 0; e < 6; e++)
                            ps[e] += __shfl_xor_sync(0xffffffffu, ps[e], d);
                    if ((lane & 3) == 0) {
#pragma unroll
                        for (int rh = 0; rh < 2; rh++) {
                            int m = m0w + mb * 16 + (lane >> 2) + rh * 8;
#pragma unroll
                            for (int cc = 0; cc < 3; cc++)
                                part[(m * 4 + wn) * 3 + cc] = ps[rh * 3 + cc];
                        }
                    }
                }
            }

            if (t & 1) __syncthreads();
        }
    }

    // ---- tail: output for j7 (part synced by loop's final barrier) ----
    if (tid < 384) {
        int m = tid & 127;
        int cc = tid >> 7;
        float s = qb2s[cc];
#pragma unroll
        for (int v = 0; v < 4; v++) s += part[(m * 4 + v) * 3 + cc];
        out[((unsigned)cc * W + (j0 + 7)) * H + i0 + m] =
            1.f / (1.f + __expf(-s));
    }
}

// ---------------------------------------------------------------------------
extern "C" void kernel_launch(void* const* d_in, const int* in_sizes, int n_in,
                              void* d_out, int out_size)
{
    const float* x   = (const float*)d_in[0];
    const float* y   = (const float*)d_in[1];
    const float* bw0 = (const float*)d_in[2];
    const float* bb0 = (const float*)d_in[3];
    const float* bw1 = (const float*)d_in[4];
    const float* bb1 = (const float*)d_in[5];
    const float* pw1 = (const float*)d_in[6];
    const float* pb1 = (const float*)d_in[7];
    const float* pw2 = (const float*)d_in[8];
    const float* pb2 = (const float*)d_in[9];
    const float* qw1 = (const float*)d_in[10];
    const float* qb1 = (const float*)d_in[11];
    const float* qw2 = (const float*)d_in[12];
    const float* qb2 = (const float*)d_in[13];
    float* out = (float*)d_out;

    cudaFuncSetAttribute(fused_mma_kernel,
                         cudaFuncAttributeMaxDynamicSharedMemorySize, SMEM_TOTAL);

    pack_qw1_kernel<<<128, 256>>>(qw1);
    branch_kernel<<<dim3(H / 16, 2), 256>>>(x, y, bw0, bb0, bw1, bb1,
                                            pw1, pb1, pw2, pb2);
    fused_mma_kernel<<<dim3(8, 128), 512, SMEM_TOTAL>>>(qb1, qw2, qb2, out);
}

// round 15
// speedup vs baseline: 1.2768x; 1.0869x over previous
#include <cuda_runtime.h>
#include <cuda_bf16.h>
#include <cuda_fp16.h>
#include <cstdint>

#define H 1024
#define W 1024
#define HID 256
#define C 3

typedef unsigned long long u64t;

// ---------------------------------------------------------------------------
// global scratch
// ---------------------------------------------------------------------------
__device__ __align__(16) __half g_fxh[H * HID];
__device__ __align__(16) __half g_fyh[W * HID];
// qw1 as fp16, SW128-swizzled K-major tiles. chunk c (k0=64c): 32KB at c*32768
__device__ __align__(16) unsigned char g_qpack[4 * 32768];

// ---------------- fast sine (scalar, branch kernel) ------------------------
__device__ __forceinline__ float fast_sin(float x) {
    const float INV_PI = 0.318309886183790671f;
    float k = rintf(x * INV_PI);
    float r = fmaf(-k, 3.14159274101257324f, x);
    r = fmaf(k, 8.74227765734758577e-8f, r);
    float s = r * r;
    float p = fmaf(s, 2.75573192e-6f, -1.98412698e-4f);
    p = fmaf(s, p, 8.33333333e-3f);
    p = fmaf(s, p, -1.66666667e-1f);
    float res = fmaf(s * r, p, r);
    int ki = (int)k;
    return (ki & 1) ? -res : res;
}

// ---------------- f32x2 packed helpers -------------------------------------
__device__ __forceinline__ u64t pk2(float lo, float hi) {
    u64t r;
    asm("mov.b64 %0, {%1, %2};" : "=l"(r)
        : "r"(__float_as_uint(lo)), "r"(__float_as_uint(hi)));
    return r;
}
__device__ __forceinline__ void upk2(u64t v, float& lo, float& hi) {
    uint32_t a, b;
    asm("mov.b64 {%0, %1}, %2;" : "=r"(a), "=r"(b) : "l"(v));
    lo = __uint_as_float(a);
    hi = __uint_as_float(b);
}
__device__ __forceinline__ u64t f2fma(u64t a, u64t b, u64t c) {
    u64t r;
    asm("fma.rn.f32x2 %0, %1, %2, %3;" : "=l"(r) : "l"(a), "l"(b), "l"(c));
    return r;
}

// ---------------- misc PTX helpers -----------------------------------------
__device__ __forceinline__ uint32_t smem_u32(const void* p) {
    uint32_t a;
    asm("{ .reg .u64 t; cvta.to.shared.u64 t, %1; cvt.u32.u64 %0, t; }"
        : "=r"(a) : "l"(p));
    return a;
}
__device__ __forceinline__ void ldsm_x4(uint32_t* r, uint32_t addr) {
    asm volatile("ldmatrix.sync.aligned.m8n8.x4.shared.b16 {%0,%1,%2,%3}, [%4];"
                 : "=r"(r[0]), "=r"(r[1]), "=r"(r[2]), "=r"(r[3]) : "r"(addr));
}
__device__ __forceinline__ void mma_f16(float* c, const uint32_t* a,
                                        const uint32_t* b) {
    asm volatile(
        "mma.sync.aligned.m16n8k16.row.col.f32.f16.f16.f32 "
        "{%0,%1,%2,%3}, {%4,%5,%6,%7}, {%8,%9}, {%0,%1,%2,%3};"
        : "+f"(c[0]), "+f"(c[1]), "+f"(c[2]), "+f"(c[3])
        : "r"(a[0]), "r"(a[1]), "r"(a[2]), "r"(a[3]), "r"(b[0]), "r"(b[1]));
}
#define CP_ASYNC16(dst, src) \
    asm volatile("cp.async.cg.shared.global [%0], [%1], 16;" \
                 :: "r"(dst), "l"(src))
#define CP_COMMIT()  asm volatile("cp.async.commit_group;")
#define CP_WAIT0()   asm volatile("cp.async.wait_group 0;" ::: "memory")

__device__ __forceinline__ uint32_t packh2(float hi, float lo) {
    uint32_t r;
    asm("cvt.rn.f16x2.f32 %0, %1, %2;" : "=r"(r) : "f"(hi), "f"(lo));
    return r;
}
__device__ __forceinline__ uint32_t hmul2(uint32_t a, uint32_t b) {
    uint32_t r;
    asm("mul.rn.f16x2 %0, %1, %2;" : "=r"(r) : "r"(a), "r"(b));
    return r;
}

// ---------------- kernel 0: pack+swizzle qw1 to fp16 -----------------------
__global__ void pack_qw1_kernel(const float* __restrict__ qw1) {
    int idx = blockIdx.x * 256 + threadIdx.x;
    int n = idx >> 7;
    int kw = idx & 127;
    int k = kw * 2;
    int cch = k >> 6;
    int kk = k & 63;
    float w0 = qw1[n * HID + k];
    float w1 = qw1[n * HID + k + 1];
    uint32_t hw = packh2(w1, w0);
    uint32_t off = ((n >> 3) << 10) + ((n & 7) << 7) + kk * 2;
    uint32_t sw = off ^ ((off >> 3) & 0x70);
    *(uint32_t*)(g_qpack + cch * 32768 + sw) = hw;
}

// ---------------- kernel 1: branch + premerge (fp16 outputs) ---------------
__device__ __forceinline__ void dense_layer(
    const float (*hin)[HID], float (*hout)[HID],
    const float* __restrict__ pw, const float* __restrict__ pb, int t)
{
    float acc[16];
    float bias = pb[t];
#pragma unroll
    for (int r = 0; r < 16; r++) acc[r] = bias;
    const float4* pw4 = (const float4*)pw;
#pragma unroll 4
    for (int k4 = 0; k4 < HID / 4; k4++) {
        float4 w4 = pw4[t * (HID / 4) + k4];
#pragma unroll
        for (int r = 0; r < 16; r++) {
            float4 hv = *(const float4*)&hin[r][k4 * 4];
            acc[r] = fmaf(hv.x, w4.x, acc[r]);
            acc[r] = fmaf(hv.y, w4.y, acc[r]);
            acc[r] = fmaf(hv.z, w4.z, acc[r]);
            acc[r] = fmaf(hv.w, w4.w, acc[r]);
        }
    }
#pragma unroll
    for (int r = 0; r < 16; r++) hout[r][t] = fast_sin(acc[r]);
}

__global__ void branch_kernel(
    const float* __restrict__ x, const float* __restrict__ y,
    const float* __restrict__ bw0, const float* __restrict__ bb0,
    const float* __restrict__ bw1, const float* __restrict__ bb1,
    const float* __restrict__ pw1, const float* __restrict__ pb1,
    const float* __restrict__ pw2, const float* __restrict__ pb2)
{
    int axis = blockIdx.y;
    const float* coord = axis ? y : x;
    const float* bw = axis ? bw1 : bw0;
    const float* bb = axis ? bb1 : bb0;
    __half* outf = axis ? g_fyh : g_fxh;
    int r0 = blockIdx.x * 16;
    int t = threadIdx.x;

    __shared__ __align__(16) float hA[16][HID];
    __shared__ __align__(16) float hB[16][HID];

    float w = bw[t], b = bb[t];
#pragma unroll
    for (int r = 0; r < 16; r++)
        hA[r][t] = fast_sin(fmaf(coord[r0 + r], w, b));
    __syncthreads();
    dense_layer(hA, hB, pw1, pb1, t);
    __syncthreads();
    dense_layer(hB, hA, pw2, pb2, t);
    __syncthreads();
#pragma unroll
    for (int r = 0; r < 16; r++)
        outf[(r0 + r) * HID + t] = __float2half_rn(hA[r][t]);
}

// ---------------- kernel 2: fragment-level A, fx SMEM-resident -------------
// grid (8, 128): i0 = bx*128, j in [by*8, by*8+8). 512 threads = 16 warps
// (4M x 4N), warp tile 32x64. fx tile (64KB, swizzled chunks) + B (128KB)
// both staged ONCE per CTA. A fragment = ldsm(fx) * fy-broadcast in regs.
// SMEM map:
//   0      qb1s 1K | 1024 qw2s 3K | 4096 qb2s | 4608 fyh 2x512B
//   5632   part[128][4][3] f32 (6KB)
//   13312  B 128KB (4 x 32KB)
//   144384 fx 64KB (4 chunks x 16KB, A-tile layout)
#define SM_QB1  0
#define SM_QW2  1024
#define SM_QB2  4096
#define SM_FYH  4608
#define SM_PART 5632
#define SM_B    13312
#define SM_FX   144384
#define SMEM_TOTAL 209920

__global__ __launch_bounds__(512, 1)
void fused_mma_kernel(
    const float* __restrict__ qb1, const float* __restrict__ qw2,
    const float* __restrict__ qb2, float* __restrict__ out)
{
    extern __shared__ __align__(1024) char smem[];
    const uint32_t sb = smem_u32(smem);
    const int tid = threadIdx.x;
    const int wid = tid >> 5;
    const int lane = tid & 31;
    const int wm = wid & 3;
    const int wn = wid >> 2;
    const int m0w = wm * 32;
    const int n0w = wn * 64;
    const int i0 = blockIdx.x * 128;
    const int j0 = blockIdx.y * 8;

    float* qb1s = (float*)(smem + SM_QB1);
    float* qw2s = (float*)(smem + SM_QW2);
    float* qb2s = (float*)(smem + SM_QB2);
    uint32_t* fyhs = (uint32_t*)(smem + SM_FYH);   // 2 buffers x 128 h2 words
    float* part = (float*)(smem + SM_PART);

    // ---- one-time staging: B (16 lines/thr) + fx swizzled (8 lines/thr) ---
    {
        const char* src = (const char*)g_qpack;
        uint32_t dst = sb + SM_B;
#pragma unroll
        for (int e = 0; e < 16; e++) {
            uint32_t off = (uint32_t)(e * 512 + tid) * 16;
            CP_ASYNC16(dst + off, src + off);
        }
        // fx: row rA2 = tid/4, two 16B segs (tid&3)*2, +1 per chunk
        int rA2 = tid >> 2;
        int sbase = (tid & 3) * 2;
        uint32_t rowo = ((rA2 >> 3) << 10) + ((rA2 & 7) << 7);
        uint32_t rx = (uint32_t)((rA2 & 7) << 4);
        const char* fsrc = (const char*)(g_fxh + (size_t)(i0 + rA2) * HID);
#pragma unroll
        for (int c = 0; c < 4; c++) {
#pragma unroll
            for (int e = 0; e < 2; e++) {
                uint32_t seg = (uint32_t)(sbase + e) * 16;
                CP_ASYNC16(sb + SM_FX + c * 16384 + rowo + (seg ^ rx),
                           fsrc + c * 128 + seg);
            }
        }
        CP_COMMIT();
    }
    if (tid < 256) qb1s[tid] = qb1[tid];
    if (tid >= 256 && tid < 384)
        fyhs[tid - 256] = ((const uint32_t*)(g_fyh + (size_t)j0 * HID))[tid - 256];
    for (int e = tid; e < 3 * HID; e += 512) qw2s[e] = qw2[e];
    if (tid < 3) qb2s[tid] = qb2[tid];
    CP_WAIT0();
    __syncthreads();          // fx/B/fyh/smalls all visible

    // ---- LDSM per-thread row/col components ----
    uint32_t rowA[2], xorA[2], colA;
    uint32_t rowB[4], xorB[4], colB;
    colA = (uint32_t)((lane >> 4) << 4);
#pragma unroll
    for (int mb = 0; mb < 2; mb++) {
        int r = m0w + mb * 16 + (lane & 15);
        rowA[mb] = ((r >> 3) << 10) + ((r & 7) << 7);
        xorA[mb] = (uint32_t)((r & 7) << 4);
    }
    colB = (uint32_t)(((lane >> 3) & 1) << 4);
#pragma unroll
    for (int nb = 0; nb < 4; nb++) {
        int r = n0w + nb * 16 + (lane & 7) + ((lane >> 4) << 3);
        rowB[nb] = ((r >> 3) << 10) + ((r & 7) << 7);
        xorB[nb] = (uint32_t)((r & 7) << 4);
    }

    float acc[2][8][4];
#pragma unroll
    for (int mb = 0; mb < 2; mb++)
#pragma unroll
        for (int nx = 0; nx < 8; nx++)
#pragma unroll
            for (int e = 0; e < 4; e++) acc[mb][nx][e] = 0.f;

    // ---- flat pipeline: t = j*4 + c ; sync every 2 steps ----
    for (int t = 0; t < 32; t++) {
        const int jj = t >> 2;
        const int c = t & 3;

        if (c == 0) {
            // final output store for j-1 (part synced at end of t-1)
            if (jj >= 1 && tid < 384) {
                int m = tid & 127;
                int cc = tid >> 7;
                float s = qb2s[cc];
#pragma unroll
                for (int v = 0; v < 4; v++) s += part[(m * 4 + v) * 3 + cc];
                out[((unsigned)cc * W + (j0 + jj - 1)) * H + i0 + m] =
                    1.f / (1.f + __expf(-s));
            }
            if (jj < 7 && tid < 128)
                fyhs[((jj + 1) & 1) * 128 + tid] =
                    ((const uint32_t*)(g_fyh + (size_t)(j0 + jj + 1) * HID))[tid];
        }

        // MMA chunk c: A fragment = ldsm(fx chunk c) * fy broadcast
        {
            const uint32_t astg = sb + SM_FX + (uint32_t)((t & 3) * 16384);
            const uint32_t bstg = sb + SM_B + (uint32_t)((t & 3) * 32768);
            const uint32_t* fyw = fyhs + (jj & 1) * 128 + (t & 3) * 32 + (lane & 3);
#pragma unroll
            for (int s = 0; s < 4; s++) {
                const uint32_t ks = (uint32_t)(s * 32);
                uint32_t fy20 = fyw[8 * s];
                uint32_t fy21 = fyw[8 * s + 4];
                uint32_t ah[2][4];
#pragma unroll
                for (int mb = 0; mb < 2; mb++) {
                    ldsm_x4(ah[mb], astg + rowA[mb] + ((colA + ks) ^ xorA[mb]));
                    ah[mb][0] = hmul2(ah[mb][0], fy20);
                    ah[mb][1] = hmul2(ah[mb][1], fy20);
                    ah[mb][2] = hmul2(ah[mb][2], fy21);
                    ah[mb][3] = hmul2(ah[mb][3], fy21);
                }
#pragma unroll
                for (int nb = 0; nb < 4; nb++) {
                    uint32_t bh[4];
                    ldsm_x4(bh, bstg + rowB[nb] + ((colB + ks) ^ xorB[nb]));
#pragma unroll
                    for (int mb = 0; mb < 2; mb++) {
                        mma_f16(acc[mb][nb * 2 + 0], ah[mb], bh + 0);
                        mma_f16(acc[mb][nb * 2 + 1], ah[mb], bh + 2);
                    }
                }
            }
        }

        // ---- epilogue at end of each j: bias + MUFU sin + f32x2 GEMV ----
        if (c == 3) {
            u64t pr[12];
#pragma unroll
            for (int e = 0; e < 12; e++) pr[e] = pk2(0.f, 0.f);
#pragma unroll
            for (int mb = 0; mb < 2; mb++) {
#pragma unroll
                for (int nx = 0; nx < 8; nx++) {
                    int n = n0w + nx * 8 + (lane & 3) * 2;
                    float b0 = qb1s[n], b1 = qb1s[n + 1];
                    u64t w0 = *(const u64t*)(qw2s + n);
                    u64t w1 = *(const u64t*)(qw2s + 256 + n);
                    u64t w2 = *(const u64t*)(qw2s + 512 + n);
#pragma unroll
                    for (int rh = 0; rh < 2; rh++) {
                        float s0 = acc[mb][nx][rh * 2] + b0;
                        float s1 = acc[mb][nx][rh * 2 + 1] + b1;
                        acc[mb][nx][rh * 2] = 0.f;
                        acc[mb][nx][rh * 2 + 1] = 0.f;
                        u64t h2 = pk2(__sinf(s0), __sinf(s1));
                        int slot = (mb * 2 + rh) * 3;
                        pr[slot + 0] = f2fma(h2, w0, pr[slot + 0]);
                        pr[slot + 1] = f2fma(h2, w1, pr[slot + 1]);
                        pr[slot + 2] = f2fma(h2, w2, pr[slot + 2]);
                    }
                }
            }
            float p[12];
#pragma unroll
            for (int e = 0; e < 12; e++) {
                float lo, hi;
                upk2(pr[e], lo, hi);
                p[e] = lo + hi;
            }
#pragma unroll
            for (int d = 1; d <= 2; d <<= 1)
#pragma unroll
                for (int e = 0; e < 12; e++)
                    p[e] += __shfl_xor_sync(0xffffffffu, p[e], d);

            if ((lane & 3) == 0) {
#pragma unroll
                for (int mb = 0; mb < 2; mb++)
#pragma unroll
                    for (int rh = 0; rh < 2; rh++) {
                        int m = m0w + mb * 16 + (lane >> 2) + rh * 8;
#pragma unroll
                        for (int cc = 0; cc < 3; cc++)
                            part[(m * 4 + wn) * 3 + cc] = p[(mb * 2 + rh) * 3 + cc];
                    }
            }
        }

        if (t & 1) __syncthreads();
    }

    // ---- tail: output for j7 (part synced by loop's final barrier) ----
    if (tid < 384) {
        int m = tid & 127;
        int cc = tid >> 7;
        float s = qb2s[cc];
#pragma unroll
        for (int v = 0; v < 4; v++) s += part[(m * 4 + v) * 3 + cc];
        out[((unsigned)cc * W + (j0 + 7)) * H + i0 + m] =
            1.f / (1.f + __expf(-s));
    }
}

// ---------------------------------------------------------------------------
extern "C" void kernel_launch(void* const* d_in, const int* in_sizes, int n_in,
                              void* d_out, int out_size)
{
    const float* x   = (const float*)d_in[0];
    const float* y   = (const float*)d_in[1];
    const float* bw0 = (const float*)d_in[2];
    const float* bb0 = (const float*)d_in[3];
    const float* bw1 = (const float*)d_in[4];
    const float* bb1 = (const float*)d_in[5];
    const float* pw1 = (const float*)d_in[6];
    const float* pb1 = (const float*)d_in[7];
    const float* pw2 = (const float*)d_in[8];
    const float* pb2 = (const float*)d_in[9];
    const float* qw1 = (const float*)d_in[10];
    const float* qb1 = (const float*)d_in[11];
    const float* qw2 = (const float*)d_in[12];
    const float* qb2 = (const float*)d_in[13];
    float* out = (float*)d_out;

    cudaFuncSetAttribute(fused_mma_kernel,
                         cudaFuncAttributeMaxDynamicSharedMemorySize, SMEM_TOTAL);

    pack_qw1_kernel<<<128, 256>>>(qw1);
    branch_kernel<<<dim3(H / 16, 2), 256>>>(x, y, bw0, bb0, bw1, bb1,
                                            pw1, pb1, pw2, pb2);
    fused_mma_kernel<<<dim3(8, 128), 512, SMEM_TOTAL>>>(qb1, qw2, qb2, out);
}

// round 16
// speedup vs baseline: 1.3252x; 1.0379x over previous
#include <cuda_runtime.h>
#include <cuda_bf16.h>
#include <cuda_fp16.h>
#include <cstdint>

#define H 1024
#define W 1024
#define HID 256
#define C 3

typedef unsigned long long u64t;

// ---------------------------------------------------------------------------
// global scratch
// ---------------------------------------------------------------------------
__device__ __align__(16) __half g_fxh[H * HID];
__device__ __align__(16) __half g_fyh[W * HID];
// qw1 as fp16, SW128-swizzled K-major tiles. chunk c (k0=64c): 32KB at c*32768
__device__ __align__(16) unsigned char g_qpack[4 * 32768];

// ---------------- fast sine (scalar, branch kernel) ------------------------
__device__ __forceinline__ float fast_sin(float x) {
    const float INV_PI = 0.318309886183790671f;
    float k = rintf(x * INV_PI);
    float r = fmaf(-k, 3.14159274101257324f, x);
    r = fmaf(k, 8.74227765734758577e-8f, r);
    float s = r * r;
    float p = fmaf(s, 2.75573192e-6f, -1.98412698e-4f);
    p = fmaf(s, p, 8.33333333e-3f);
    p = fmaf(s, p, -1.66666667e-1f);
    float res = fmaf(s * r, p, r);
    int ki = (int)k;
    return (ki & 1) ? -res : res;
}

// ---------------- f32x2 packed helpers -------------------------------------
__device__ __forceinline__ u64t pk2(float lo, float hi) {
    u64t r;
    asm("mov.b64 %0, {%1, %2};" : "=l"(r)
        : "r"(__float_as_uint(lo)), "r"(__float_as_uint(hi)));
    return r;
}
__device__ __forceinline__ void upk2(u64t v, float& lo, float& hi) {
    uint32_t a, b;
    asm("mov.b64 {%0, %1}, %2;" : "=r"(a), "=r"(b) : "l"(v));
    lo = __uint_as_float(a);
    hi = __uint_as_float(b);
}
__device__ __forceinline__ u64t f2fma(u64t a, u64t b, u64t c) {
    u64t r;
    asm("fma.rn.f32x2 %0, %1, %2, %3;" : "=l"(r) : "l"(a), "l"(b), "l"(c));
    return r;
}

// ---------------- misc PTX helpers -----------------------------------------
__device__ __forceinline__ uint32_t smem_u32(const void* p) {
    uint32_t a;
    asm("{ .reg .u64 t; cvta.to.shared.u64 t, %1; cvt.u32.u64 %0, t; }"
        : "=r"(a) : "l"(p));
    return a;
}
__device__ __forceinline__ void ldsm_x4(uint32_t* r, uint32_t addr) {
    asm volatile("ldmatrix.sync.aligned.m8n8.x4.shared.b16 {%0,%1,%2,%3}, [%4];"
                 : "=r"(r[0]), "=r"(r[1]), "=r"(r[2]), "=r"(r[3]) : "r"(addr));
}
__device__ __forceinline__ void mma_f16(float* c, const uint32_t* a,
                                        const uint32_t* b) {
    asm volatile(
        "mma.sync.aligned.m16n8k16.row.col.f32.f16.f16.f32 "
        "{%0,%1,%2,%3}, {%4,%5,%6,%7}, {%8,%9}, {%0,%1,%2,%3};"
        : "+f"(c[0]), "+f"(c[1]), "+f"(c[2]), "+f"(c[3])
        : "r"(a[0]), "r"(a[1]), "r"(a[2]), "r"(a[3]), "r"(b[0]), "r"(b[1]));
}
// C = 0 variant: writes acc fresh (used at c==0, s==0 of each j)
__device__ __forceinline__ void mma_f16_z(float* c, const uint32_t* a,
                                          const uint32_t* b) {
    asm volatile(
        "{\n\t.reg .f32 z;\n\tmov.f32 z, 0f00000000;\n\t"
        "mma.sync.aligned.m16n8k16.row.col.f32.f16.f16.f32 "
        "{%0,%1,%2,%3}, {%4,%5,%6,%7}, {%8,%9}, {z,z,z,z};\n\t}"
        : "=f"(c[0]), "=f"(c[1]), "=f"(c[2]), "=f"(c[3])
        : "r"(a[0]), "r"(a[1]), "r"(a[2]), "r"(a[3]), "r"(b[0]), "r"(b[1]));
}
#define CP_ASYNC16(dst, src) \
    asm volatile("cp.async.cg.shared.global [%0], [%1], 16;" \
                 :: "r"(dst), "l"(src))
#define CP_COMMIT()  asm volatile("cp.async.commit_group;")
#define CP_WAIT0()   asm volatile("cp.async.wait_group 0;" ::: "memory")

__device__ __forceinline__ uint32_t packh2(float hi, float lo) {
    uint32_t r;
    asm("cvt.rn.f16x2.f32 %0, %1, %2;" : "=r"(r) : "f"(hi), "f"(lo));
    return r;
}
__device__ __forceinline__ uint32_t hmul2(uint32_t a, uint32_t b) {
    uint32_t r;
    asm("mul.rn.f16x2 %0, %1, %2;" : "=r"(r) : "r"(a), "r"(b));
    return r;
}

// ---------------- kernel 0: pack+swizzle qw1 to fp16 -----------------------
__global__ void pack_qw1_kernel(const float* __restrict__ qw1) {
    int idx = blockIdx.x * 256 + threadIdx.x;
    int n = idx >> 7;
    int kw = idx & 127;
    int k = kw * 2;
    int cch = k >> 6;
    int kk = k & 63;
    float w0 = qw1[n * HID + k];
    float w1 = qw1[n * HID + k + 1];
    uint32_t hw = packh2(w1, w0);
    uint32_t off = ((n >> 3) << 10) + ((n & 7) << 7) + kk * 2;
    uint32_t sw = off ^ ((off >> 3) & 0x70);
    *(uint32_t*)(g_qpack + cch * 32768 + sw) = hw;
}

// ---------------- kernel 1: branch + premerge (fp16 outputs) ---------------
__device__ __forceinline__ void dense_layer(
    const float (*hin)[HID], float (*hout)[HID],
    const float* __restrict__ pw, const float* __restrict__ pb, int t)
{
    float acc[16];
    float bias = pb[t];
#pragma unroll
    for (int r = 0; r < 16; r++) acc[r] = bias;
    const float4* pw4 = (const float4*)pw;
#pragma unroll 4
    for (int k4 = 0; k4 < HID / 4; k4++) {
        float4 w4 = pw4[t * (HID / 4) + k4];
#pragma unroll
        for (int r = 0; r < 16; r++) {
            float4 hv = *(const float4*)&hin[r][k4 * 4];
            acc[r] = fmaf(hv.x, w4.x, acc[r]);
            acc[r] = fmaf(hv.y, w4.y, acc[r]);
            acc[r] = fmaf(hv.z, w4.z, acc[r]);
            acc[r] = fmaf(hv.w, w4.w, acc[r]);
        }
    }
#pragma unroll
    for (int r = 0; r < 16; r++) hout[r][t] = fast_sin(acc[r]);
}

__global__ void branch_kernel(
    const float* __restrict__ x, const float* __restrict__ y,
    const float* __restrict__ bw0, const float* __restrict__ bb0,
    const float* __restrict__ bw1, const float* __restrict__ bb1,
    const float* __restrict__ pw1, const float* __restrict__ pb1,
    const float* __restrict__ pw2, const float* __restrict__ pb2)
{
    int axis = blockIdx.y;
    const float* coord = axis ? y : x;
    const float* bw = axis ? bw1 : bw0;
    const float* bb = axis ? bb1 : bb0;
    __half* outf = axis ? g_fyh : g_fxh;
    int r0 = blockIdx.x * 16;
    int t = threadIdx.x;

    __shared__ __align__(16) float hA[16][HID];
    __shared__ __align__(16) float hB[16][HID];

    float w = bw[t], b = bb[t];
#pragma unroll
    for (int r = 0; r < 16; r++)
        hA[r][t] = fast_sin(fmaf(coord[r0 + r], w, b));
    __syncthreads();
    dense_layer(hA, hB, pw1, pb1, t);
    __syncthreads();
    dense_layer(hB, hA, pw2, pb2, t);
    __syncthreads();
#pragma unroll
    for (int r = 0; r < 16; r++)
        outf[(r0 + r) * HID + t] = __float2half_rn(hA[r][t]);
}

// ---------------- kernel 2: fragment-level A, 1 barrier per j --------------
// grid (8, 128): i0 = bx*128, j in [by*8, by*8+8). 512 threads = 16 warps
// (4M x 4N), warp tile 32x64. fx (64KB) + B (128KB) staged once. A fragment
// = ldsm(fx) * fy-broadcast. acc initialized via zero-C MMA at (c0,s0).
// part double-buffered (mod-2 by j); ONE __syncthreads per j (after c3).
// SMEM map:
//   0      qb1s 1K | 1024 qw2s 3K | 4096 qb2s | 4608 fyh 2x512B
//   5632   part 2 x 6KB
//   18432  B 128KB (4 x 32KB)
//   149504 fx 64KB (4 chunks x 16KB, A-tile layout)
#define SM_QB1  0
#define SM_QW2  1024
#define SM_QB2  4096
#define SM_FYH  4608
#define SM_PART 5632
#define PART_SZ 6144
#define SM_B    18432
#define SM_FX   149504
#define SMEM_TOTAL 215040

__global__ __launch_bounds__(512, 1)
void fused_mma_kernel(
    const float* __restrict__ qb1, const float* __restrict__ qw2,
    const float* __restrict__ qb2, float* __restrict__ out)
{
    extern __shared__ __align__(1024) char smem[];
    const uint32_t sb = smem_u32(smem);
    const int tid = threadIdx.x;
    const int wid = tid >> 5;
    const int lane = tid & 31;
    const int wm = wid & 3;
    const int wn = wid >> 2;
    const int m0w = wm * 32;
    const int n0w = wn * 64;
    const int i0 = blockIdx.x * 128;
    const int j0 = blockIdx.y * 8;

    float* qb1s = (float*)(smem + SM_QB1);
    float* qw2s = (float*)(smem + SM_QW2);
    float* qb2s = (float*)(smem + SM_QB2);
    uint32_t* fyhs = (uint32_t*)(smem + SM_FYH);   // 2 buffers x 128 h2 words

    // ---- one-time staging: B (16 lines/thr) + fx swizzled (8 lines/thr) ---
    {
        const char* src = (const char*)g_qpack;
        uint32_t dst = sb + SM_B;
#pragma unroll
        for (int e = 0; e < 16; e++) {
            uint32_t off = (uint32_t)(e * 512 + tid) * 16;
            CP_ASYNC16(dst + off, src + off);
        }
        // fx: row rA2 = tid/4, two 16B segs (tid&3)*2, +1 per chunk
        int rA2 = tid >> 2;
        int sbase = (tid & 3) * 2;
        uint32_t rowo = ((rA2 >> 3) << 10) + ((rA2 & 7) << 7);
        uint32_t rx = (uint32_t)((rA2 & 7) << 4);
        const char* fsrc = (const char*)(g_fxh + (size_t)(i0 + rA2) * HID);
#pragma unroll
        for (int c = 0; c < 4; c++) {
#pragma unroll
            for (int e = 0; e < 2; e++) {
                uint32_t seg = (uint32_t)(sbase + e) * 16;
                CP_ASYNC16(sb + SM_FX + c * 16384 + rowo + (seg ^ rx),
                           fsrc + c * 128 + seg);
            }
        }
        CP_COMMIT();
    }
    if (tid < 256) qb1s[tid] = qb1[tid];
    if (tid >= 256 && tid < 384)
        fyhs[tid - 256] = ((const uint32_t*)(g_fyh + (size_t)j0 * HID))[tid - 256];
    for (int e = tid; e < 3 * HID; e += 512) qw2s[e] = qw2[e];
    if (tid < 3) qb2s[tid] = qb2[tid];
    CP_WAIT0();
    __syncthreads();          // fx/B/fyh/smalls all visible

    // ---- LDSM per-thread row/col components ----
    uint32_t rowA[2], xorA[2], colA;
    uint32_t rowB[4], xorB[4], colB;
    colA = (uint32_t)((lane >> 4) << 4);
#pragma unroll
    for (int mb = 0; mb < 2; mb++) {
        int r = m0w + mb * 16 + (lane & 15);
        rowA[mb] = ((r >> 3) << 10) + ((r & 7) << 7);
        xorA[mb] = (uint32_t)((r & 7) << 4);
    }
    colB = (uint32_t)(((lane >> 3) & 1) << 4);
#pragma unroll
    for (int nb = 0; nb < 4; nb++) {
        int r = n0w + nb * 16 + (lane & 7) + ((lane >> 4) << 3);
        rowB[nb] = ((r >> 3) << 10) + ((r & 7) << 7);
        xorB[nb] = (uint32_t)((r & 7) << 4);
    }

    float acc[2][8][4];
#pragma unroll
    for (int mb = 0; mb < 2; mb++)
#pragma unroll
        for (int nx = 0; nx < 8; nx++)
#pragma unroll
            for (int e = 0; e < 4; e++) acc[mb][nx][e] = 0.f;

    // ---- flat pipeline: t = j*4 + c ; ONE sync per j (after c3) ----
    for (int t = 0; t < 32; t++) {
        const int jj = t >> 2;
        const int c = t & 3;
        const bool czero = (c == 0);

        if (c == 0) {
            // final output store for j-1 (part buf (jj-1)&1, synced at end
            // of jj-1)
            if (jj >= 1 && tid < 384) {
                const float* partb =
                    (const float*)(smem + SM_PART + ((jj - 1) & 1) * PART_SZ);
                int m = tid & 127;
                int cc = tid >> 7;
                float s = qb2s[cc];
#pragma unroll
                for (int v = 0; v < 4; v++) s += partb[(m * 4 + v) * 3 + cc];
                out[((unsigned)cc * W + (j0 + jj - 1)) * H + i0 + m] =
                    1.f / (1.f + __expf(-s));
            }
            if (jj < 7 && tid < 128)
                fyhs[((jj + 1) & 1) * 128 + tid] =
                    ((const uint32_t*)(g_fyh + (size_t)(j0 + jj + 1) * HID))[tid];
        }

        // MMA chunk c: A fragment = ldsm(fx chunk c) * fy broadcast
        {
            const uint32_t astg = sb + SM_FX + (uint32_t)((t & 3) * 16384);
            const uint32_t bstg = sb + SM_B + (uint32_t)((t & 3) * 32768);
            const uint32_t* fyw = fyhs + (jj & 1) * 128 + (t & 3) * 32 + (lane & 3);
#pragma unroll
            for (int s = 0; s < 4; s++) {
                const uint32_t ks = (uint32_t)(s * 32);
                uint32_t fy20 = fyw[8 * s];
                uint32_t fy21 = fyw[8 * s + 4];
                uint32_t ah[2][4];
#pragma unroll
                for (int mb = 0; mb < 2; mb++) {
                    ldsm_x4(ah[mb], astg + rowA[mb] + ((colA + ks) ^ xorA[mb]));
                    ah[mb][0] = hmul2(ah[mb][0], fy20);
                    ah[mb][1] = hmul2(ah[mb][1], fy20);
                    ah[mb][2] = hmul2(ah[mb][2], fy21);
                    ah[mb][3] = hmul2(ah[mb][3], fy21);
                }
#pragma unroll
                for (int nb = 0; nb < 4; nb++) {
                    uint32_t bh[4];
                    ldsm_x4(bh, bstg + rowB[nb] + ((colB + ks) ^ xorB[nb]));
                    if (s == 0 && czero) {
#pragma unroll
                        for (int mb = 0; mb < 2; mb++) {
                            mma_f16_z(acc[mb][nb * 2 + 0], ah[mb], bh + 0);
                            mma_f16_z(acc[mb][nb * 2 + 1], ah[mb], bh + 2);
                        }
                    } else {
#pragma unroll
                        for (int mb = 0; mb < 2; mb++) {
                            mma_f16(acc[mb][nb * 2 + 0], ah[mb], bh + 0);
                            mma_f16(acc[mb][nb * 2 + 1], ah[mb], bh + 2);
                        }
                    }
                }
            }
        }

        // ---- epilogue at end of each j: bias + MUFU sin + f32x2 GEMV ----
        if (c == 3) {
            float* partb = (float*)(smem + SM_PART + (jj & 1) * PART_SZ);
            u64t pr[12];
#pragma unroll
            for (int e = 0; e < 12; e++) pr[e] = pk2(0.f, 0.f);
#pragma unroll
            for (int mb = 0; mb < 2; mb++) {
#pragma unroll
                for (int nx = 0; nx < 8; nx++) {
                    int n = n0w + nx * 8 + (lane & 3) * 2;
                    float b0 = qb1s[n], b1 = qb1s[n + 1];
                    u64t w0 = *(const u64t*)(qw2s + n);
                    u64t w1 = *(const u64t*)(qw2s + 256 + n);
                    u64t w2 = *(const u64t*)(qw2s + 512 + n);
#pragma unroll
                    for (int rh = 0; rh < 2; rh++) {
                        float s0 = acc[mb][nx][rh * 2] + b0;
                        float s1 = acc[mb][nx][rh * 2 + 1] + b1;
                        u64t h2 = pk2(__sinf(s0), __sinf(s1));
                        int slot = (mb * 2 + rh) * 3;
                        pr[slot + 0] = f2fma(h2, w0, pr[slot + 0]);
                        pr[slot + 1] = f2fma(h2, w1, pr[slot + 1]);
                        pr[slot + 2] = f2fma(h2, w2, pr[slot + 2]);
                    }
                }
            }
            float p[12];
#pragma unroll
            for (int e = 0; e < 12; e++) {
                float lo, hi;
                upk2(pr[e], lo, hi);
                p[e] = lo + hi;
            }
#pragma unroll
            for (int d = 1; d <= 2; d <<= 1)
#pragma unroll
                for (int e = 0; e < 12; e++)
                    p[e] += __shfl_xor_sync(0xffffffffu, p[e], d);

            if ((lane & 3) == 0) {
#pragma unroll
                for (int mb = 0; mb < 2; mb++)
#pragma unroll
                    for (int rh = 0; rh < 2; rh++) {
                        int m = m0w + mb * 16 + (lane >> 2) + rh * 8;
#pragma unroll
                        for (int cc = 0; cc < 3; cc++)
                            partb[(m * 4 + wn) * 3 + cc] = p[(mb * 2 + rh) * 3 + cc];
                    }
            }
            __syncthreads();           // the only barrier per j
        }
    }

    // ---- tail: output for j7 (part buf 1, synced by final barrier) ----
    if (tid < 384) {
        const float* partb = (const float*)(smem + SM_PART + 1 * PART_SZ);
        int m = tid & 127;
        int cc = tid >> 7;
        float s = qb2s[cc];
#pragma unroll
        for (int v = 0; v < 4; v++) s += partb[(m * 4 + v) * 3 + cc];
        out[((unsigned)cc * W + (j0 + 7)) * H + i0 + m] =
            1.f / (1.f + __expf(-s));
    }
}

// ---------------------------------------------------------------------------
extern "C" void kernel_launch(void* const* d_in, const int* in_sizes, int n_in,
                              void* d_out, int out_size)
{
    const float* x   = (const float*)d_in[0];
    const float* y   = (const float*)d_in[1];
    const float* bw0 = (const float*)d_in[2];
    const float* bb0 = (const float*)d_in[3];
    const float* bw1 = (const float*)d_in[4];
    const float* bb1 = (const float*)d_in[5];
    const float* pw1 = (const float*)d_in[6];
    const float* pb1 = (const float*)d_in[7];
    const float* pw2 = (const float*)d_in[8];
    const float* pb2 = (const float*)d_in[9];
    const float* qw1 = (const float*)d_in[10];
    const float* qb1 = (const float*)d_in[11];
    const float* qw2 = (const float*)d_in[12];
    const float* qb2 = (const float*)d_in[13];
    float* out = (float*)d_out;

    cudaFuncSetAttribute(fused_mma_kernel,
                         cudaFuncAttributeMaxDynamicSharedMemorySize, SMEM_TOTAL);

    pack_qw1_kernel<<<128, 256>>>(qw1);
    branch_kernel<<<dim3(H / 16, 2), 256>>>(x, y, bw0, bb0, bw1, bb1,
                                            pw1, pb1, pw2, pb2);
    fused_mma_kernel<<<dim3(8, 128), 512, SMEM_TOTAL>>>(qb1, qw2, qb2, out);
}